// round 16
// baseline (speedup 1.0000x reference)
#include <cuda_runtime.h>
#include <cuda_bf16.h>

#define BB   64
#define MM   64
#define NN   64
#define OUT  512

#define U_TILE  32
#define V_TILE  128
#define THREADS 128

__global__ __launch_bounds__(THREADS) void surfeval_kernel(
    const float4* __restrict__ ctrl4,   // (B, M, N) float4 (xyzw)
    const float4* __restrict__ Nu4,     // (OUT)
    const float4* __restrict__ Nv4,     // (OUT)
    const int* __restrict__ iu,         // (OUT,4) int32
    const int* __restrict__ iv,         // (OUT,4) int32
    float* __restrict__ out)            // (B, OUT, OUT, 3)
{
    __shared__ float4 s_Nu[U_TILE];
    __shared__ int    s_row0[U_TILE];

    const int tid  = threadIdx.x;
    const int lane = tid & 31;
    const int wrp  = tid >> 5;
    const int vt   = blockIdx.x;
    const int ut   = blockIdx.y;
    const int b    = blockIdx.z;

    const int u_lo = ut * U_TILE;
    const int u_hi = u_lo + U_TILE;

    if (tid < U_TILE) {
        s_Nu[tid]   = __ldg(&Nu4[u_lo + tid]);
        s_row0[tid] = __ldg(&iu[(u_lo + tid) * 4]);
    }
    __syncthreads();

    // dense-store ownership: lane k (<24) stores row floats [4k, 4k+4) = 16B,
    // which straddle points q0, q0+1 of this warp's 32-point row segment.
    const int  keff = (lane < 24) ? lane : 23;
    const int  q0   = (4 * keff) / 3;
    const int  r    = (4 * keff) - 3 * q0;   // 0,1,2
    const bool do_store = (lane < 24);

    const int vbase = vt * V_TILE + wrp * 32;
    const int va = vbase + q0;
    const int vb = va + 1;

    const float4 nva = __ldg(&Nv4[va]);
    const float4 nvb = __ldg(&Nv4[vb]);
    const int iva = __ldg(&iv[va * 4]);
    const int ivb = __ldg(&iv[vb * 4]);

    const float4* cba = ctrl4 + ((size_t)b * MM * NN) + iva;
    const float4* cbb = ctrl4 + ((size_t)b * MM * NN) + ivb;

    // per-lane store pointer: row base + 4k floats (16B-aligned: 384*m + 16k)
    float4* op = (float4*)(out + (((size_t)b * OUT + u_lo) * OUT + vbase) * 3 + 4 * lane);
    const size_t u_stride4 = (size_t)OUT * 3 / 4;   // float4 stride per u-row

    int u = u_lo;
    #pragma unroll 1
    while (u < u_hi) {
        const int row0 = s_row0[u - u_lo];

        // rowdots for both owned points
        float4 ra0, ra1, ra2, ra3, rb0, rb1, rb2, rb3;
        {
            const float4* pa = cba + (size_t)row0 * NN;
            const float4* pb = cbb + (size_t)row0 * NN;
            #pragma unroll
            for (int l = 0; l < 4; ++l) {
                float4 c0 = pa[0], c1 = pa[1], c2 = pa[2], c3 = pa[3];
                float4 ra;
                ra.x = nva.x*c0.x + nva.y*c1.x + nva.z*c2.x + nva.w*c3.x;
                ra.y = nva.x*c0.y + nva.y*c1.y + nva.z*c2.y + nva.w*c3.y;
                ra.z = nva.x*c0.z + nva.y*c1.z + nva.z*c2.z + nva.w*c3.z;
                ra.w = nva.x*c0.w + nva.y*c1.w + nva.z*c2.w + nva.w*c3.w;
                c0 = pb[0]; c1 = pb[1]; c2 = pb[2]; c3 = pb[3];
                float4 rb;
                rb.x = nvb.x*c0.x + nvb.y*c1.x + nvb.z*c2.x + nvb.w*c3.x;
                rb.y = nvb.x*c0.y + nvb.y*c1.y + nvb.z*c2.y + nvb.w*c3.y;
                rb.z = nvb.x*c0.z + nvb.y*c1.z + nvb.z*c2.z + nvb.w*c3.z;
                rb.w = nvb.x*c0.w + nvb.y*c1.w + nvb.z*c2.w + nvb.w*c3.w;
                if (l == 0) { ra0 = ra; rb0 = rb; }
                else if (l == 1) { ra1 = ra; rb1 = rb; }
                else if (l == 2) { ra2 = ra; rb2 = rb; }
                else { ra3 = ra; rb3 = rb; }
                pa += NN; pb += NN;
            }
        }

        #pragma unroll 1
        do {
            const float4 nu = s_Nu[u - u_lo];

            float4 A, Bv;
            A.x = nu.x*ra0.x + nu.y*ra1.x + nu.z*ra2.x + nu.w*ra3.x;
            A.y = nu.x*ra0.y + nu.y*ra1.y + nu.z*ra2.y + nu.w*ra3.y;
            A.z = nu.x*ra0.z + nu.y*ra1.z + nu.z*ra2.z + nu.w*ra3.z;
            A.w = nu.x*ra0.w + nu.y*ra1.w + nu.z*ra2.w + nu.w*ra3.w;
            Bv.x = nu.x*rb0.x + nu.y*rb1.x + nu.z*rb2.x + nu.w*rb3.x;
            Bv.y = nu.x*rb0.y + nu.y*rb1.y + nu.z*rb2.y + nu.w*rb3.y;
            Bv.z = nu.x*rb0.z + nu.y*rb1.z + nu.z*rb2.z + nu.w*rb3.z;
            Bv.w = nu.x*rb0.w + nu.y*rb1.w + nu.z*rb2.w + nu.w*rb3.w;

            const float ia = __fdividef(1.0f, A.w);
            const float ib = __fdividef(1.0f, Bv.w);
            const float sax = A.x * ia,  say = A.y * ia,  saz = A.z * ia;
            const float sbx = Bv.x * ib, sby = Bv.y * ib, sbz = Bv.z * ib;

            // component pattern by r: r=0:(ax,ay,az,bx) r=1:(ay,az,bx,by) r=2:(az,bx,by,bz)
            float4 val;
            val.x = (r == 0) ? sax : ((r == 1) ? say : saz);
            val.y = (r == 0) ? say : ((r == 1) ? saz : sbx);
            val.z = (r == 0) ? saz : ((r == 1) ? sbx : sby);
            val.w = (r == 0) ? sbx : ((r == 1) ? sby : sbz);

            if (do_store) *op = val;     // one aligned STG.128, dense across lanes

            op += u_stride4;
            ++u;
        } while (u < u_hi && s_row0[u - u_lo] == row0);
    }
}

extern "C" void kernel_launch(void* const* d_in, const int* in_sizes, int n_in,
                              void* d_out, int out_size) {
    const float4* ctrl = (const float4*)d_in[0];
    const float4* Nu   = (const float4*)d_in[1];
    const float4* Nv   = (const float4*)d_in[2];
    const int*    iu   = (const int*)d_in[3];
    const int*    iv   = (const int*)d_in[4];
    float*        out  = (float*)d_out;

    dim3 grid(OUT / V_TILE, OUT / U_TILE, BB);   // (4, 16, 64) = 4096 CTAs
    surfeval_kernel<<<grid, THREADS>>>(ctrl, Nu, Nv, iu, iv, out);
}

// round 17
// speedup vs baseline: 1.1204x; 1.1204x over previous
#include <cuda_runtime.h>
#include <cuda_bf16.h>

#define BB   64
#define MM   64
#define NN   64
#define OUT  512

#define U_TILE      32
#define THREADS     128
#define V_PER_BLOCK 256   // 2 adjacent v per thread

__global__ __launch_bounds__(THREADS) void surfeval_kernel(
    const float4* __restrict__ ctrl4,   // (B, M, N) float4 (xyzw)
    const float4* __restrict__ Nu4,     // (OUT)
    const float4* __restrict__ Nv4,     // (OUT)
    const int* __restrict__ iu,         // (OUT,4) int32
    const int* __restrict__ iv,         // (OUT,4) int32
    float* __restrict__ out)            // (B, OUT, OUT, 3)
{
    __shared__ float4 s_Nu[U_TILE];
    __shared__ int    s_row0[U_TILE];

    const int tid = threadIdx.x;
    const int vt  = blockIdx.x;
    const int ut  = blockIdx.y;
    const int b   = blockIdx.z;

    const int u_lo = ut * U_TILE;
    const int u_hi = u_lo + U_TILE;

    if (tid < U_TILE) {
        s_Nu[tid]   = __ldg(&Nu4[u_lo + tid]);
        s_row0[tid] = __ldg(&iu[(u_lo + tid) * 4]);
    }
    __syncthreads();

    const int v0 = vt * V_PER_BLOCK + 2 * tid;   // this thread: v0, v0+1
    const float4 nva = __ldg(&Nv4[v0]);
    const float4 nvb = __ldg(&Nv4[v0 + 1]);
    const int iva = __ldg(&iv[v0 * 4]);
    const int ivb = __ldg(&iv[(v0 + 1) * 4]);
    const int d   = ivb - iva;                   // 0 or 1

    // 5-column weight vectors over columns iva..iva+4 (wb shifted by d)
    const float wa0 = nva.x, wa1 = nva.y, wa2 = nva.z, wa3 = nva.w, wa4 = 0.0f;
    const float wb0 = d ? 0.0f  : nvb.x;
    const float wb1 = d ? nvb.x : nvb.y;
    const float wb2 = d ? nvb.y : nvb.z;
    const float wb3 = d ? nvb.z : nvb.w;
    const float wb4 = d ? nvb.w : 0.0f;

    const float4* cb = ctrl4 + ((size_t)b * MM * NN) + iva;

    // 6 floats (24B, 8B-aligned) per thread per u-row, dense across warp
    float* op = out + (((size_t)b * OUT + u_lo) * OUT + v0) * 3;
    const size_t u_stride = (size_t)OUT * 3;

    int u = u_lo;
    #pragma unroll 1
    while (u < u_hi) {
        const int row0 = s_row0[u - u_lo];

        // shared 5-column loads, two rowdot sets (one per v)
        float4 ra0, ra1, ra2, ra3, rb0, rb1, rb2, rb3;
        {
            const float4* p = cb + (size_t)row0 * NN;
            #pragma unroll
            for (int l = 0; l < 4; ++l) {
                const float4 c0 = p[0], c1 = p[1], c2 = p[2], c3 = p[3], c4 = p[4];
                float4 ra, rb;
                ra.x = wa0*c0.x + wa1*c1.x + wa2*c2.x + wa3*c3.x + wa4*c4.x;
                ra.y = wa0*c0.y + wa1*c1.y + wa2*c2.y + wa3*c3.y + wa4*c4.y;
                ra.z = wa0*c0.z + wa1*c1.z + wa2*c2.z + wa3*c3.z + wa4*c4.z;
                ra.w = wa0*c0.w + wa1*c1.w + wa2*c2.w + wa3*c3.w + wa4*c4.w;
                rb.x = wb0*c0.x + wb1*c1.x + wb2*c2.x + wb3*c3.x + wb4*c4.x;
                rb.y = wb0*c0.y + wb1*c1.y + wb2*c2.y + wb3*c3.y + wb4*c4.y;
                rb.z = wb0*c0.z + wb1*c1.z + wb2*c2.z + wb3*c3.z + wb4*c4.z;
                rb.w = wb0*c0.w + wb1*c1.w + wb2*c2.w + wb3*c3.w + wb4*c4.w;
                if      (l == 0) { ra0 = ra; rb0 = rb; }
                else if (l == 1) { ra1 = ra; rb1 = rb; }
                else if (l == 2) { ra2 = ra; rb2 = rb; }
                else             { ra3 = ra; rb3 = rb; }
                p += NN;
            }
        }

        // sweep all u sharing this span
        #pragma unroll 1
        do {
            const float4 nu = s_Nu[u - u_lo];

            float4 A, Bv;
            A.x = nu.x*ra0.x + nu.y*ra1.x + nu.z*ra2.x + nu.w*ra3.x;
            A.y = nu.x*ra0.y + nu.y*ra1.y + nu.z*ra2.y + nu.w*ra3.y;
            A.z = nu.x*ra0.z + nu.y*ra1.z + nu.z*ra2.z + nu.w*ra3.z;
            A.w = nu.x*ra0.w + nu.y*ra1.w + nu.z*ra2.w + nu.w*ra3.w;
            Bv.x = nu.x*rb0.x + nu.y*rb1.x + nu.z*rb2.x + nu.w*rb3.x;
            Bv.y = nu.x*rb0.y + nu.y*rb1.y + nu.z*rb2.y + nu.w*rb3.y;
            Bv.z = nu.x*rb0.z + nu.y*rb1.z + nu.z*rb2.z + nu.w*rb3.z;
            Bv.w = nu.x*rb0.w + nu.y*rb1.w + nu.z*rb2.w + nu.w*rb3.w;

            const float ia = __fdividef(1.0f, A.w);
            const float ib = __fdividef(1.0f, Bv.w);

            float2* o2 = (float2*)op;
            o2[0] = make_float2(A.x * ia,  A.y * ia);   // x0 y0
            o2[1] = make_float2(A.z * ia,  Bv.x * ib);  // z0 x1
            o2[2] = make_float2(Bv.y * ib, Bv.z * ib);  // y1 z1

            op += u_stride;
            ++u;
        } while (u < u_hi && s_row0[u - u_lo] == row0);
    }
}

extern "C" void kernel_launch(void* const* d_in, const int* in_sizes, int n_in,
                              void* d_out, int out_size) {
    const float4* ctrl = (const float4*)d_in[0];
    const float4* Nu   = (const float4*)d_in[1];
    const float4* Nv   = (const float4*)d_in[2];
    const int*    iu   = (const int*)d_in[3];
    const int*    iv   = (const int*)d_in[4];
    float*        out  = (float*)d_out;

    dim3 grid(OUT / V_PER_BLOCK, OUT / U_TILE, BB);   // (2, 16, 64) = 2048 CTAs
    surfeval_kernel<<<grid, THREADS>>>(ctrl, Nu, Nv, iu, iv, out);
}